// round 2
// baseline (speedup 1.0000x reference)
#include <cuda_runtime.h>

#define NN   50000
#define EE   600000
#define ETOT 650000
#define GG   50
#define INC  5
#define HID  64
#define OUTC 32
#define HEADS 4
#define BN_EPS 1e-5f

// ---------------- scratch (device globals; no allocation allowed) ----------------
__device__ __align__(16) float        g_h [NN * HID];          // layer input (post BN+relu)
__device__ __align__(16) float        g_hW[NN * HEADS * HID];  // [N, H*DOUT] (stride = H*DOUT)
__device__ __align__(16) float        g_es[NN * HEADS];
__device__ __align__(16) float        g_ed[NN * HEADS];
__device__ __align__(16) unsigned int g_m [NN * HEADS];        // encoded float max
__device__ __align__(16) float        g_s [NN * HEADS];        // softmax denom
__device__ __align__(16) float        g_e [ETOT * HEADS];      // per-edge e, then ex
__device__ __align__(16) float        g_hn[NN * HID];          // aggregated (pre-BN)
__device__ double g_bnsum[HID];
__device__ double g_bnsq [HID];
__device__ float  g_scale[HID];
__device__ float  g_shift[HID];
__device__ float        g_counts[GG];
__device__ float        g_gsum  [GG * OUTC];
__device__ unsigned int g_gmaxu [GG * OUTC];
__device__ float        g_gemb  [GG * OUTC];

// ordered-float encoding for atomicMax on unsigned (init 0 < any real encoding)
__device__ __forceinline__ unsigned int fenc(float f) {
    unsigned int u = __float_as_uint(f);
    return (u & 0x80000000u) ? ~u : (u | 0x80000000u);
}
__device__ __forceinline__ float fdec(unsigned int u) {
    return __uint_as_float((u & 0x80000000u) ? (u ^ 0x80000000u) : ~u);
}

// ---------------- kernels ----------------
__global__ void k_encoder(const float* __restrict__ x, const float* __restrict__ w,
                          const float* __restrict__ b) {
    int i = blockIdx.x * blockDim.x + threadIdx.x;
    if (i >= NN * HID) return;
    int n = i / HID, c = i % HID;
    float acc = b[c];
#pragma unroll
    for (int k = 0; k < INC; k++) acc += x[n * INC + k] * w[k * HID + c];
    g_h[i] = acc;
}

// one block per node; blockDim = HEADS*DOUT. Computes hW row + es/ed.
template <int DOUT>
__global__ void __launch_bounds__(HEADS * DOUT)
k_transform(const float* __restrict__ W, const float* __restrict__ as_,
            const float* __restrict__ ad_) {
    const int HD = HEADS * DOUT;
    int n = blockIdx.x;
    int tid = threadIdx.x;
    __shared__ float sh[HID];
    __shared__ float ps[HEADS * DOUT];
    __shared__ float pd[HEADS * DOUT];
    if (tid < HID) sh[tid] = g_h[n * HID + tid];
    __syncthreads();
    float acc = 0.f;
#pragma unroll
    for (int k = 0; k < HID; k++) acc = fmaf(sh[k], W[k * HD + tid], acc);
    g_hW[n * HD + tid] = acc;
    int h = tid / DOUT, c = tid % DOUT;
    ps[tid] = acc * as_[h * DOUT + c];
    pd[tid] = acc * ad_[h * DOUT + c];
    __syncthreads();
    if (tid < 2 * HEADS) {
        int hh = tid >> 1;
        const float* p = (tid & 1) ? pd : ps;
        float s = 0.f;
#pragma unroll
        for (int c2 = 0; c2 < DOUT; c2++) s += p[hh * DOUT + c2];
        if (tid & 1) g_ed[n * HEADS + hh] = s;
        else         g_es[n * HEADS + hh] = s;
    }
}

__global__ void k_edge_max(const int* __restrict__ ei) {
    int e = blockIdx.x * blockDim.x + threadIdx.x;
    if (e >= ETOT) return;
    int s, d;
    if (e < EE) { s = ei[e]; d = ei[EE + e]; } else { s = d = e - EE; }
    float4 a = *(const float4*)&g_es[s * 4];
    float4 b = *(const float4*)&g_ed[d * 4];
    float v0 = a.x + b.x, v1 = a.y + b.y, v2 = a.z + b.z, v3 = a.w + b.w;
    v0 = v0 > 0.f ? v0 : 0.2f * v0;
    v1 = v1 > 0.f ? v1 : 0.2f * v1;
    v2 = v2 > 0.f ? v2 : 0.2f * v2;
    v3 = v3 > 0.f ? v3 : 0.2f * v3;
    *(float4*)&g_e[e * 4] = make_float4(v0, v1, v2, v3);
    atomicMax(&g_m[d * 4 + 0], fenc(v0));
    atomicMax(&g_m[d * 4 + 1], fenc(v1));
    atomicMax(&g_m[d * 4 + 2], fenc(v2));
    atomicMax(&g_m[d * 4 + 3], fenc(v3));
}

__global__ void k_edge_exp(const int* __restrict__ ei) {
    int e = blockIdx.x * blockDim.x + threadIdx.x;
    if (e >= ETOT) return;
    int d = (e < EE) ? ei[EE + e] : (e - EE);
    float4 v = *(const float4*)&g_e[e * 4];
    uint4 mu = *(const uint4*)&g_m[d * 4];
    float e0 = expf(v.x - fdec(mu.x));
    float e1 = expf(v.y - fdec(mu.y));
    float e2 = expf(v.z - fdec(mu.z));
    float e3 = expf(v.w - fdec(mu.w));
    *(float4*)&g_e[e * 4] = make_float4(e0, e1, e2, e3);
    atomicAdd(&g_s[d * 4 + 0], e0);
    atomicAdd(&g_s[d * 4 + 1], e1);
    atomicAdd(&g_s[d * 4 + 2], e2);
    atomicAdd(&g_s[d * 4 + 3], e3);
}

// per-edge gather of hW[src], head-reduced, atomicAdd into g_hn (pre-scaled by 1/HEADS)
template <int DOUT>
__global__ void __launch_bounds__(256)
k_aggregate(const int* __restrict__ ei) {
    const int HD = HEADS * DOUT;
    const int EPB = 256 / DOUT;
    __shared__ int   ssrc[EPB];
    __shared__ int   sdst[EPB];
    __shared__ float sal[EPB][HEADS];
    int tid = threadIdx.x;
    long base = (long)blockIdx.x * EPB;
    if (tid < EPB) {
        long e = base + tid;
        if (e < ETOT) {
            int s, d;
            if (e < EE) { s = ei[e]; d = ei[EE + e]; } else { s = d = (int)(e - EE); }
            ssrc[tid] = s; sdst[tid] = d;
            float4 ex = *(const float4*)&g_e[e * 4];
            float4 sm = *(const float4*)&g_s[d * 4];
            sal[tid][0] = ex.x / (sm.x + 1e-16f);
            sal[tid][1] = ex.y / (sm.y + 1e-16f);
            sal[tid][2] = ex.z / (sm.z + 1e-16f);
            sal[tid][3] = ex.w / (sm.w + 1e-16f);
        }
    }
    __syncthreads();
    int le = tid / DOUT, c = tid % DOUT;
    long e = base + le;
    if (e >= ETOT) return;
    int s = ssrc[le], d = sdst[le];
    const float* hp = &g_hW[(long)s * HD + c];
    float val = 0.f;
#pragma unroll
    for (int h = 0; h < HEADS; h++) val = fmaf(hp[h * DOUT], sal[le][h], val);
    atomicAdd(&g_hn[d * DOUT + c], 0.25f * val);
}

template <int DOUT>
__global__ void __launch_bounds__(256)
k_bn_partial() {
    int tid = threadIdx.x;
    int c = tid % DOUT;  // invariant under stride (gridDim*256 % DOUT == 0)
    float s = 0.f, q = 0.f;
    for (long i = (long)blockIdx.x * blockDim.x + tid; i < (long)NN * DOUT;
         i += (long)gridDim.x * blockDim.x) {
        float v = g_hn[i];
        s += v; q += v * v;
    }
    __shared__ float sm[256], qm[256];
    sm[tid] = s; qm[tid] = q;
    __syncthreads();
    for (int off = 128; off >= DOUT; off >>= 1) {
        if (tid < off) { sm[tid] += sm[tid + off]; qm[tid] += qm[tid + off]; }
        __syncthreads();
    }
    if (tid < DOUT) {
        atomicAdd(&g_bnsum[c], (double)sm[tid]);
        atomicAdd(&g_bnsq[c],  (double)qm[tid]);
    }
}

template <int DOUT>
__global__ void k_bn_finalize(const float* __restrict__ gamma, const float* __restrict__ beta) {
    int c = threadIdx.x;
    if (c >= DOUT) return;
    float mean = (float)(g_bnsum[c] / (double)NN);
    float var  = (float)(g_bnsq[c] / (double)NN) - mean * mean;
    var = fmaxf(var, 0.f);
    float sc = gamma[c] * rsqrtf(var + BN_EPS);
    g_scale[c] = sc;
    g_shift[c] = beta[c] - mean * sc;
}

template <int DOUT>
__global__ void k_bn_apply_relu() {  // layers 0,1: write back into g_h with relu
    long i = (long)blockIdx.x * blockDim.x + threadIdx.x;
    if (i >= (long)NN * DOUT) return;
    int c = i % DOUT;
    float y = fmaf(g_scale[c], g_hn[i], g_shift[c]);
    g_h[i] = fmaxf(y, 0.f);
}

template <int DOUT>
__global__ void k_bn_apply_out(float* __restrict__ out) {  // final layer: no relu
    long i = (long)blockIdx.x * blockDim.x + threadIdx.x;
    if (i >= (long)NN * DOUT) return;
    int c = i % DOUT;
    out[i] = fmaf(g_scale[c], g_hn[i], g_shift[c]);
}

__global__ void k_counts(const int* __restrict__ batch) {
    int n = blockIdx.x * blockDim.x + threadIdx.x;
    if (n < NN) atomicAdd(&g_counts[batch[n]], 1.0f);
}

__global__ void k_pool(const int* __restrict__ batch, const float* __restrict__ hf) {
    long i = (long)blockIdx.x * blockDim.x + threadIdx.x;
    if (i >= (long)NN * OUTC) return;
    int n = i / OUTC, c = i % OUTC;
    int g = batch[n];
    float v = hf[i];
    atomicAdd(&g_gsum[g * OUTC + c], v);
    atomicMax(&g_gmaxu[g * OUTC + c], fenc(v));
}

__global__ void k_gemb(float* __restrict__ out_gemb) {
    int i = blockIdx.x * blockDim.x + threadIdx.x;
    if (i >= GG * OUTC) return;
    int g = i / OUTC;
    float cnt = g_counts[g];
    float sum = g_gsum[i];
    float mean = sum / fmaxf(cnt, 1.f);
    float mx = (cnt > 0.f) ? fdec(g_gmaxu[i]) : 0.f;
    float v = (mean + mx + sum) * (1.f / 3.f);
    g_gemb[i] = v;
    out_gemb[i] = v;
}

__global__ void k_heads(const float* __restrict__ ew1, const float* __restrict__ eb1,
                        const float* __restrict__ ew2, const float* __restrict__ eb2,
                        const float* __restrict__ mw1, const float* __restrict__ mb1,
                        const float* __restrict__ mw2, const float* __restrict__ mb2,
                        float* __restrict__ out_eth, float* __restrict__ out_man) {
    int g = threadIdx.x;
    if (g >= GG) return;
    float ge[OUTC];
#pragma unroll
    for (int k = 0; k < OUTC; k++) ge[k] = g_gemb[g * OUTC + k];
    float oe = eb2[0];
#pragma unroll
    for (int j = 0; j < OUTC / 2; j++) {
        float a = eb1[j];
#pragma unroll
        for (int k = 0; k < OUTC; k++) a = fmaf(ge[k], ew1[k * (OUTC / 2) + j], a);
        oe = fmaf(fmaxf(a, 0.f), ew2[j], oe);
    }
    out_eth[g] = 1.f / (1.f + expf(-oe));
    float om = mb2[0];
#pragma unroll
    for (int j = 0; j < OUTC / 2; j++) {
        float a = mb1[j];
#pragma unroll
        for (int k = 0; k < OUTC; k++) a = fmaf(ge[k], mw1[k * (OUTC / 2) + j], a);
        om = fmaf(fmaxf(a, 0.f), mw2[j], om);
    }
    out_man[g] = 1.f / (1.f + expf(-om));
}

// ---------------- host ----------------
template <int DOUT>
static void run_layer(const float* W, const float* as_, const float* ad_,
                      const float* gamma, const float* beta, const int* ei,
                      float* final_out,
                      void* pm, void* ps, void* phn, void* pbs, void* pbq) {
    cudaMemsetAsync(pm,  0, (size_t)NN * HEADS * sizeof(unsigned int));
    cudaMemsetAsync(ps,  0, (size_t)NN * HEADS * sizeof(float));
    cudaMemsetAsync(phn, 0, (size_t)NN * DOUT * sizeof(float));
    cudaMemsetAsync(pbs, 0, (size_t)DOUT * sizeof(double));
    cudaMemsetAsync(pbq, 0, (size_t)DOUT * sizeof(double));
    k_transform<DOUT><<<NN, HEADS * DOUT>>>(W, as_, ad_);
    k_edge_max<<<(ETOT + 255) / 256, 256>>>(ei);
    k_edge_exp<<<(ETOT + 255) / 256, 256>>>(ei);
    constexpr int EPB = 256 / DOUT;
    k_aggregate<DOUT><<<(ETOT + EPB - 1) / EPB, 256>>>(ei);
    k_bn_partial<DOUT><<<296, 256>>>();
    k_bn_finalize<DOUT><<<1, DOUT>>>(gamma, beta);
    if (final_out)
        k_bn_apply_out<DOUT><<<(NN * DOUT + 255) / 256, 256>>>(final_out);
    else
        k_bn_apply_relu<DOUT><<<(NN * DOUT + 255) / 256, 256>>>();
}

extern "C" void kernel_launch(void* const* d_in, const int* in_sizes, int n_in,
                              void* d_out, int out_size) {
    const float* x      = (const float*)d_in[0];
    const int*   ei     = (const int*)d_in[1];
    const int*   batch  = (const int*)d_in[2];
    const float* enc_w  = (const float*)d_in[3];
    const float* enc_b  = (const float*)d_in[4];
    // layers: w,as,ad,b,g,be per layer starting at 5 (biases b{l} cancel in BN -> skipped)
    const float* W0 = (const float*)d_in[5],  *A0s = (const float*)d_in[6],  *A0d = (const float*)d_in[7];
    const float* G0 = (const float*)d_in[9],  *B0  = (const float*)d_in[10];
    const float* W1 = (const float*)d_in[11], *A1s = (const float*)d_in[12], *A1d = (const float*)d_in[13];
    const float* G1 = (const float*)d_in[15], *B1  = (const float*)d_in[16];
    const float* W2 = (const float*)d_in[17], *A2s = (const float*)d_in[18], *A2d = (const float*)d_in[19];
    const float* G2 = (const float*)d_in[21], *B2  = (const float*)d_in[22];
    const float* ew1 = (const float*)d_in[23], *eb1 = (const float*)d_in[24];
    const float* ew2 = (const float*)d_in[25], *eb2 = (const float*)d_in[26];
    const float* mw1 = (const float*)d_in[27], *mb1 = (const float*)d_in[28];
    const float* mw2 = (const float*)d_in[29], *mb2 = (const float*)d_in[30];

    float* out      = (float*)d_out;
    float* out_h    = out;
    float* out_gemb = out + (size_t)NN * OUTC;
    float* out_eth  = out_gemb + GG * OUTC;
    float* out_man  = out_eth + GG;

    void *pm, *ps, *phn, *pbs, *pbq, *pc, *pgs, *pgm;
    cudaGetSymbolAddress(&pm,  g_m);
    cudaGetSymbolAddress(&ps,  g_s);
    cudaGetSymbolAddress(&phn, g_hn);
    cudaGetSymbolAddress(&pbs, g_bnsum);
    cudaGetSymbolAddress(&pbq, g_bnsq);
    cudaGetSymbolAddress(&pc,  g_counts);
    cudaGetSymbolAddress(&pgs, g_gsum);
    cudaGetSymbolAddress(&pgm, g_gmaxu);

    k_encoder<<<(NN * HID + 255) / 256, 256>>>(x, enc_w, enc_b);

    run_layer<HID>(W0, A0s, A0d, G0, B0, ei, nullptr, pm, ps, phn, pbs, pbq);
    run_layer<HID>(W1, A1s, A1d, G1, B1, ei, nullptr, pm, ps, phn, pbs, pbq);
    run_layer<OUTC>(W2, A2s, A2d, G2, B2, ei, out_h, pm, ps, phn, pbs, pbq);

    cudaMemsetAsync(pc,  0, GG * sizeof(float));
    cudaMemsetAsync(pgs, 0, GG * OUTC * sizeof(float));
    cudaMemsetAsync(pgm, 0, GG * OUTC * sizeof(unsigned int));
    k_counts<<<(NN + 255) / 256, 256>>>(batch);
    k_pool<<<(NN * OUTC + 255) / 256, 256>>>(batch, out_h);
    k_gemb<<<(GG * OUTC + 63) / 64, 64>>>(out_gemb);
    k_heads<<<1, 64>>>(ew1, eb1, ew2, eb2, mw1, mb1, mw2, mb2, out_eth, out_man);
}

// round 3
// speedup vs baseline: 3.3338x; 3.3338x over previous
#include <cuda_runtime.h>
#include <float.h>

#define NN   50000
#define EE   600000
#define ETOT 650000
#define GG   50
#define INC  5
#define HID  64
#define OUTC 32
#define HEADS 4
#define BN_EPS 1e-5f
#define NSC  50176   // 49*1024, padded scan size >= NN+1

// ---------------- scratch (device globals) ----------------
__device__ __align__(16) float g_h [NN * HID];          // encoder output
__device__ __align__(16) float g_hW[NN * HEADS * HID];  // [N, H*DOUT]
__device__ __align__(16) float g_es[NN * HEADS];
__device__ __align__(16) float g_ed[NN * HEADS];
__device__ __align__(16) float g_hn[NN * HID];          // aggregated (pre-BN)
__device__ int g_cnt[NSC];
__device__ int g_bsum[49];
__device__ int g_boff[49];
__device__ int g_off[NN + 1];
__device__ int g_cur[NN];
__device__ int g_csr[ETOT];
__device__ double g_bnsum[HID];
__device__ double g_bnsq [HID];
__device__ float  g_scale[HID];
__device__ float  g_shift[HID];
__device__ float        g_counts[GG];
__device__ float        g_gsum  [GG * OUTC];
__device__ unsigned int g_gmaxu [GG * OUTC];
__device__ float        g_gemb  [GG * OUTC];

__device__ __forceinline__ unsigned int fenc(float f) {
    unsigned int u = __float_as_uint(f);
    return (u & 0x80000000u) ? ~u : (u | 0x80000000u);
}
__device__ __forceinline__ float fdec(unsigned int u) {
    return __uint_as_float((u & 0x80000000u) ? (u ^ 0x80000000u) : ~u);
}
__device__ __forceinline__ float lrelu(float v) { return v > 0.f ? v : 0.2f * v; }

// ---------------- CSR build ----------------
__global__ void k_hist(const int* __restrict__ ei) {
    int e = blockIdx.x * blockDim.x + threadIdx.x;
    if (e >= ETOT) return;
    int d = (e < EE) ? ei[EE + e] : (e - EE);
    atomicAdd(&g_cnt[d], 1);
}
__global__ void k_scan_a() {   // 49 blocks x 1024
    __shared__ int sm[1024];
    int t = threadIdx.x;
    sm[t] = g_cnt[blockIdx.x * 1024 + t];
    __syncthreads();
    for (int o = 512; o; o >>= 1) {
        if (t < o) sm[t] += sm[t + o];
        __syncthreads();
    }
    if (t == 0) g_bsum[blockIdx.x] = sm[0];
}
__global__ void k_scan_b() {   // 1 thread
    int acc = 0;
    for (int b = 0; b < 49; b++) { g_boff[b] = acc; acc += g_bsum[b]; }
}
__global__ void k_scan_c() {   // 49 blocks x 1024, Hillis-Steele inclusive -> exclusive
    __shared__ int sm[1024];
    int t = threadIdx.x;
    int i = blockIdx.x * 1024 + t;
    int v = g_cnt[i];
    sm[t] = v;
    __syncthreads();
    for (int o = 1; o < 1024; o <<= 1) {
        int u = (t >= o) ? sm[t - o] : 0;
        __syncthreads();
        sm[t] += u;
        __syncthreads();
    }
    int ex = g_boff[blockIdx.x] + sm[t] - v;
    if (i <= NN) g_off[i] = ex;
    if (i < NN)  g_cur[i] = ex;
}
__global__ void k_fill(const int* __restrict__ ei) {
    int e = blockIdx.x * blockDim.x + threadIdx.x;
    if (e >= ETOT) return;
    int s, d;
    if (e < EE) { s = ei[e]; d = ei[EE + e]; } else { s = d = e - EE; }
    int pos = atomicAdd(&g_cur[d], 1);
    g_csr[pos] = s;
}

// ---------------- encoder ----------------
__global__ void k_encoder(const float* __restrict__ x, const float* __restrict__ w,
                          const float* __restrict__ b) {
    int i = blockIdx.x * blockDim.x + threadIdx.x;
    if (i >= NN * HID) return;
    int n = i / HID, c = i % HID;
    float acc = b[c];
#pragma unroll
    for (int k = 0; k < INC; k++) acc += x[n * INC + k] * w[k * HID + c];
    g_h[i] = acc;
}

// ---------------- transform: h@W (+fused input BN/relu, +fused es/ed epilogue) ----------------
// thread = 4 columns x 8 nodes. block 256 threads.
template <int DOUT, bool BNIN>
__global__ void __launch_bounds__(256)
k_transform2(const float* __restrict__ in, const float* __restrict__ W,
             const float* __restrict__ as_, const float* __restrict__ ad_) {
    constexpr int HD    = 4 * DOUT;
    constexpr int COLT  = HD / 4;      // 64 or 32 column-threads
    constexpr int NGRP  = 256 / COLT;  // 4 or 8 node groups
    constexpr int NODES = NGRP * 8;    // 32 or 64 nodes per block
    constexpr int LPH   = DOUT / 4;    // lanes per head (16 or 8)
    __shared__ float sh[NODES * HID];

    int t = threadIdx.x;
    int nbase = blockIdx.x * NODES;

    for (int i = t; i < NODES * HID; i += 256) {
        int n = nbase + i / HID;
        int k = i % HID;
        float v = 0.f;
        if (n < NN) {
            v = in[n * HID + k];
            if (BNIN) v = fmaxf(fmaf(g_scale[k], v, g_shift[k]), 0.f);
        }
        sh[i] = v;
    }
    __syncthreads();

    int tx = t % COLT;
    int g  = t / COLT;
    int j0 = g * 8;

    float4 acc[8];
#pragma unroll
    for (int j = 0; j < 8; j++) acc[j] = make_float4(0.f, 0.f, 0.f, 0.f);

#pragma unroll 4
    for (int k = 0; k < HID; k++) {
        float4 wv = *(const float4*)&W[k * HD + 4 * tx];
#pragma unroll
        for (int j = 0; j < 8; j++) {
            float hv = sh[(j0 + j) * HID + k];
            acc[j].x = fmaf(hv, wv.x, acc[j].x);
            acc[j].y = fmaf(hv, wv.y, acc[j].y);
            acc[j].z = fmaf(hv, wv.z, acc[j].z);
            acc[j].w = fmaf(hv, wv.w, acc[j].w);
        }
    }

    float4 as4 = *(const float4*)&as_[4 * tx];
    float4 ad4 = *(const float4*)&ad_[4 * tx];
    int head = (4 * tx) / DOUT;

#pragma unroll
    for (int j = 0; j < 8; j++) {
        int n = nbase + j0 + j;
        if (n < NN) *(float4*)&g_hW[(size_t)n * HD + 4 * tx] = acc[j];
        float pes = acc[j].x * as4.x + acc[j].y * as4.y + acc[j].z * as4.z + acc[j].w * as4.w;
        float ped = acc[j].x * ad4.x + acc[j].y * ad4.y + acc[j].z * ad4.z + acc[j].w * ad4.w;
#pragma unroll
        for (int o = LPH / 2; o; o >>= 1) {
            pes += __shfl_xor_sync(0xffffffffu, pes, o);
            ped += __shfl_xor_sync(0xffffffffu, ped, o);
        }
        if ((tx % LPH) == 0 && n < NN) {
            g_es[n * 4 + head] = pes;
            g_ed[n * 4 + head] = ped;
        }
    }
}

// ---------------- fused GAT aggregation: warp per dst node, no atomics ----------------
template <int DOUT>
__global__ void __launch_bounds__(256)
k_agg() {
    constexpr int HD = 4 * DOUT;
    int warp = threadIdx.x >> 5, lane = threadIdx.x & 31;
    int n = blockIdx.x * 8 + warp;
    if (n >= NN) return;
    int beg = g_off[n], end = g_off[n + 1];

    float4 ed4 = *(const float4*)&g_ed[n * 4];

    // pass 1: per-head max over incoming edges
    float m0 = -FLT_MAX, m1 = -FLT_MAX, m2 = -FLT_MAX, m3 = -FLT_MAX;
    for (int i = beg + lane; i < end; i += 32) {
        int s = g_csr[i];
        float4 es4 = *(const float4*)&g_es[s * 4];
        m0 = fmaxf(m0, lrelu(es4.x + ed4.x));
        m1 = fmaxf(m1, lrelu(es4.y + ed4.y));
        m2 = fmaxf(m2, lrelu(es4.z + ed4.z));
        m3 = fmaxf(m3, lrelu(es4.w + ed4.w));
    }
#pragma unroll
    for (int o = 16; o; o >>= 1) {
        m0 = fmaxf(m0, __shfl_xor_sync(0xffffffffu, m0, o));
        m1 = fmaxf(m1, __shfl_xor_sync(0xffffffffu, m1, o));
        m2 = fmaxf(m2, __shfl_xor_sync(0xffffffffu, m2, o));
        m3 = fmaxf(m3, __shfl_xor_sync(0xffffffffu, m3, o));
    }
    float mh  = (lane == 0) ? m0 : (lane == 1) ? m1 : (lane == 2) ? m2 : m3;
    float edh = (lane == 0) ? ed4.x : (lane == 1) ? ed4.y : (lane == 2) ? ed4.z : ed4.w;

    // pass 2: accumulate unnormalized weighted sum + per-head denom
    float sacc = 0.f;
    float4 a0 = make_float4(0.f, 0.f, 0.f, 0.f);
    float4 a1 = make_float4(0.f, 0.f, 0.f, 0.f);
    for (int i = beg; i < end; i++) {
        int s = g_csr[i];  // broadcast load
        float ex = 0.f;
        if (lane < 4) {
            float e = lrelu(g_es[s * 4 + lane] + edh);
            ex = expf(e - mh);
            sacc += ex;
        }
        const float4* hp = (const float4*)(g_hW + (size_t)s * HD);
        if (DOUT == 64) {
            float exA = __shfl_sync(0xffffffffu, ex, lane >> 4);
            float exB = __shfl_sync(0xffffffffu, ex, 2 + (lane >> 4));
            float4 v0 = hp[lane];
            float4 v1 = hp[32 + lane];
            a0.x = fmaf(v0.x, exA, a0.x); a0.y = fmaf(v0.y, exA, a0.y);
            a0.z = fmaf(v0.z, exA, a0.z); a0.w = fmaf(v0.w, exA, a0.w);
            a1.x = fmaf(v1.x, exB, a1.x); a1.y = fmaf(v1.y, exB, a1.y);
            a1.z = fmaf(v1.z, exB, a1.z); a1.w = fmaf(v1.w, exB, a1.w);
        } else {
            float exA = __shfl_sync(0xffffffffu, ex, lane >> 3);
            float4 v0 = hp[lane];
            a0.x = fmaf(v0.x, exA, a0.x); a0.y = fmaf(v0.y, exA, a0.y);
            a0.z = fmaf(v0.z, exA, a0.z); a0.w = fmaf(v0.w, exA, a0.w);
        }
    }

    if (DOUT == 64) {
        float sA = __shfl_sync(0xffffffffu, sacc, lane >> 4) + 1e-16f;
        float sB = __shfl_sync(0xffffffffu, sacc, 2 + (lane >> 4)) + 1e-16f;
        float rx = a0.x / sA + a1.x / sB;
        float ry = a0.y / sA + a1.y / sB;
        float rz = a0.z / sA + a1.z / sB;
        float rw = a0.w / sA + a1.w / sB;
        rx += __shfl_xor_sync(0xffffffffu, rx, 16);
        ry += __shfl_xor_sync(0xffffffffu, ry, 16);
        rz += __shfl_xor_sync(0xffffffffu, rz, 16);
        rw += __shfl_xor_sync(0xffffffffu, rw, 16);
        if (lane < 16)
            *(float4*)&g_hn[n * 64 + 4 * lane] =
                make_float4(0.25f * rx, 0.25f * ry, 0.25f * rz, 0.25f * rw);
    } else {
        float sA = __shfl_sync(0xffffffffu, sacc, lane >> 3) + 1e-16f;
        float rx = a0.x / sA, ry = a0.y / sA, rz = a0.z / sA, rw = a0.w / sA;
        rx += __shfl_xor_sync(0xffffffffu, rx, 8);
        ry += __shfl_xor_sync(0xffffffffu, ry, 8);
        rz += __shfl_xor_sync(0xffffffffu, rz, 8);
        rw += __shfl_xor_sync(0xffffffffu, rw, 8);
        rx += __shfl_xor_sync(0xffffffffu, rx, 16);
        ry += __shfl_xor_sync(0xffffffffu, ry, 16);
        rz += __shfl_xor_sync(0xffffffffu, rz, 16);
        rw += __shfl_xor_sync(0xffffffffu, rw, 16);
        if (lane < 8)
            *(float4*)&g_hn[n * 32 + 4 * lane] =
                make_float4(0.25f * rx, 0.25f * ry, 0.25f * rz, 0.25f * rw);
    }
}

// ---------------- BatchNorm ----------------
template <int DOUT>
__global__ void __launch_bounds__(256)
k_bn_partial() {
    int tid = threadIdx.x;
    int c = tid % DOUT;  // gridDim*256 % DOUT == 0
    float s = 0.f, q = 0.f;
    for (long i = (long)blockIdx.x * blockDim.x + tid; i < (long)NN * DOUT;
         i += (long)gridDim.x * blockDim.x) {
        float v = g_hn[i];
        s += v; q += v * v;
    }
    __shared__ float sm[256], qm[256];
    sm[tid] = s; qm[tid] = q;
    __syncthreads();
    for (int off = 128; off >= DOUT; off >>= 1) {
        if (tid < off) { sm[tid] += sm[tid + off]; qm[tid] += qm[tid + off]; }
        __syncthreads();
    }
    if (tid < DOUT) {
        atomicAdd(&g_bnsum[c], (double)sm[tid]);
        atomicAdd(&g_bnsq[c],  (double)qm[tid]);
    }
}
template <int DOUT>
__global__ void k_bn_finalize(const float* __restrict__ gamma, const float* __restrict__ beta) {
    int c = threadIdx.x;
    if (c >= DOUT) return;
    float mean = (float)(g_bnsum[c] / (double)NN);
    float var  = (float)(g_bnsq[c] / (double)NN) - mean * mean;
    var = fmaxf(var, 0.f);
    float sc = gamma[c] * rsqrtf(var + BN_EPS);
    g_scale[c] = sc;
    g_shift[c] = beta[c] - mean * sc;
    g_bnsum[c] = 0.0;   // self-zero for next use
    g_bnsq[c]  = 0.0;
}

// ---------------- final BN apply + pooling fused ----------------
__global__ void k_apply_pool(const int* __restrict__ batch, float* __restrict__ out_h) {
    long i = (long)blockIdx.x * blockDim.x + threadIdx.x;
    if (i >= (long)NN * OUTC) return;
    int n = i / OUTC, c = i % OUTC;
    float v = fmaf(g_scale[c], g_hn[i], g_shift[c]);
    out_h[i] = v;
    int g = batch[n];
    atomicAdd(&g_gsum[g * OUTC + c], v);
    atomicMax(&g_gmaxu[g * OUTC + c], fenc(v));
    if (c == 0) atomicAdd(&g_counts[g], 1.0f);
}

__global__ void k_gemb(float* __restrict__ out_gemb) {
    int i = blockIdx.x * blockDim.x + threadIdx.x;
    if (i >= GG * OUTC) return;
    int g = i / OUTC;
    float cnt = g_counts[g];
    float sum = g_gsum[i];
    float mean = sum / fmaxf(cnt, 1.f);
    float mx = (cnt > 0.f) ? fdec(g_gmaxu[i]) : 0.f;
    float v = (mean + mx + sum) * (1.f / 3.f);
    g_gemb[i] = v;
    out_gemb[i] = v;
}

__global__ void k_heads(const float* __restrict__ ew1, const float* __restrict__ eb1,
                        const float* __restrict__ ew2, const float* __restrict__ eb2,
                        const float* __restrict__ mw1, const float* __restrict__ mb1,
                        const float* __restrict__ mw2, const float* __restrict__ mb2,
                        float* __restrict__ out_eth, float* __restrict__ out_man) {
    int g = threadIdx.x;
    if (g >= GG) return;
    float ge[OUTC];
#pragma unroll
    for (int k = 0; k < OUTC; k++) ge[k] = g_gemb[g * OUTC + k];
    float oe = eb2[0];
#pragma unroll
    for (int j = 0; j < OUTC / 2; j++) {
        float a = eb1[j];
#pragma unroll
        for (int k = 0; k < OUTC; k++) a = fmaf(ge[k], ew1[k * (OUTC / 2) + j], a);
        oe = fmaf(fmaxf(a, 0.f), ew2[j], oe);
    }
    out_eth[g] = 1.f / (1.f + expf(-oe));
    float om = mb2[0];
#pragma unroll
    for (int j = 0; j < OUTC / 2; j++) {
        float a = mb1[j];
#pragma unroll
        for (int k = 0; k < OUTC; k++) a = fmaf(ge[k], mw1[k * (OUTC / 2) + j], a);
        om = fmaf(fmaxf(a, 0.f), mw2[j], om);
    }
    out_man[g] = 1.f / (1.f + expf(-om));
}

// ---------------- host ----------------
extern "C" void kernel_launch(void* const* d_in, const int* in_sizes, int n_in,
                              void* d_out, int out_size) {
    const float* x      = (const float*)d_in[0];
    const int*   ei     = (const int*)d_in[1];
    const int*   batch  = (const int*)d_in[2];
    const float* enc_w  = (const float*)d_in[3];
    const float* enc_b  = (const float*)d_in[4];
    const float* W0 = (const float*)d_in[5],  *A0s = (const float*)d_in[6],  *A0d = (const float*)d_in[7];
    const float* G0 = (const float*)d_in[9],  *B0  = (const float*)d_in[10];
    const float* W1 = (const float*)d_in[11], *A1s = (const float*)d_in[12], *A1d = (const float*)d_in[13];
    const float* G1 = (const float*)d_in[15], *B1  = (const float*)d_in[16];
    const float* W2 = (const float*)d_in[17], *A2s = (const float*)d_in[18], *A2d = (const float*)d_in[19];
    const float* G2 = (const float*)d_in[21], *B2  = (const float*)d_in[22];
    const float* ew1 = (const float*)d_in[23], *eb1 = (const float*)d_in[24];
    const float* ew2 = (const float*)d_in[25], *eb2 = (const float*)d_in[26];
    const float* mw1 = (const float*)d_in[27], *mb1 = (const float*)d_in[28];
    const float* mw2 = (const float*)d_in[29], *mb2 = (const float*)d_in[30];

    float* out      = (float*)d_out;
    float* out_h    = out;
    float* out_gemb = out + (size_t)NN * OUTC;
    float* out_eth  = out_gemb + GG * OUTC;
    float* out_man  = out_eth + GG;

    void *pcnt, *pbs, *pbq, *pc, *pgs, *pgm, *ph, *phn;
    cudaGetSymbolAddress(&pcnt, g_cnt);
    cudaGetSymbolAddress(&pbs,  g_bnsum);
    cudaGetSymbolAddress(&pbq,  g_bnsq);
    cudaGetSymbolAddress(&pc,   g_counts);
    cudaGetSymbolAddress(&pgs,  g_gsum);
    cudaGetSymbolAddress(&pgm,  g_gmaxu);
    cudaGetSymbolAddress(&ph,   g_h);
    cudaGetSymbolAddress(&phn,  g_hn);

    // CSR build (once; shared by all 3 layers)
    cudaMemsetAsync(pcnt, 0, NSC * sizeof(int));
    k_hist<<<(ETOT + 255) / 256, 256>>>(ei);
    k_scan_a<<<49, 1024>>>();
    k_scan_b<<<1, 1>>>();
    k_scan_c<<<49, 1024>>>();
    k_fill<<<(ETOT + 255) / 256, 256>>>(ei);

    k_encoder<<<(NN * HID + 255) / 256, 256>>>(x, enc_w, enc_b);

    cudaMemsetAsync(pbs, 0, HID * sizeof(double));
    cudaMemsetAsync(pbq, 0, HID * sizeof(double));

    // Layer 0 (DOUT=64, input = encoder output, no BN on input)
    k_transform2<64, false><<<(NN + 31) / 32, 256>>>((const float*)ph, W0, A0s, A0d);
    k_agg<64><<<(NN + 7) / 8, 256>>>();
    k_bn_partial<64><<<296, 256>>>();
    k_bn_finalize<64><<<1, 64>>>(G0, B0);

    // Layer 1 (DOUT=64, input = g_hn with BN0+relu fused)
    k_transform2<64, true><<<(NN + 31) / 32, 256>>>((const float*)phn, W1, A1s, A1d);
    k_agg<64><<<(NN + 7) / 8, 256>>>();
    k_bn_partial<64><<<296, 256>>>();
    k_bn_finalize<64><<<1, 64>>>(G1, B1);

    // Layer 2 (DOUT=32, input = g_hn with BN1+relu fused)
    k_transform2<32, true><<<(NN + 63) / 64, 256>>>((const float*)phn, W2, A2s, A2d);
    k_agg<32><<<(NN + 7) / 8, 256>>>();
    k_bn_partial<32><<<296, 256>>>();
    k_bn_finalize<32><<<1, 32>>>(G2, B2);

    // Final BN apply + pooling fused
    cudaMemsetAsync(pc,  0, GG * sizeof(float));
    cudaMemsetAsync(pgs, 0, GG * OUTC * sizeof(float));
    cudaMemsetAsync(pgm, 0, GG * OUTC * sizeof(unsigned int));
    k_apply_pool<<<(NN * OUTC + 255) / 256, 256>>>(batch, out_h);
    k_gemb<<<(GG * OUTC + 63) / 64, 64>>>(out_gemb);
    k_heads<<<1, 64>>>(ew1, eb1, ew2, eb2, mw1, mb1, mw2, mb2, out_eth, out_man);
}

// round 4
// speedup vs baseline: 4.3824x; 1.3145x over previous
#include <cuda_runtime.h>
#include <cuda_fp16.h>
#include <float.h>

#define NN   50000
#define EE   600000
#define ETOT 650000
#define GG   50
#define INC  5
#define HID  64
#define OUTC 32
#define HEADS 4
#define BN_EPS 1e-5f
#define NSC  50176   // 49*1024 >= NN+1
#define FULLM 0xffffffffu

// ---------------- scratch (device globals) ----------------
__device__ __align__(16) float    g_h [NN * HID];      // encoder output
__device__ __align__(16) unsigned g_hW[NN * 128];      // fp16 hW: up to 256 halves/row (as half2 words)
__device__ __align__(16) float    g_es[NN * HEADS];
__device__ __align__(16) float    g_ed[NN * HEADS];
__device__ __align__(16) float    g_hn[NN * HID];      // aggregated (pre-BN), fp32
__device__ int g_cnt[NSC];
__device__ int g_bsum[49];
__device__ int g_boff[49];
__device__ int g_off[NN + 1];
__device__ int g_cur[NN];
__device__ int g_csr[ETOT];
__device__ double g_bnsum[HID];   // self-zeroing (bn_finalize)
__device__ double g_bnsq [HID];
__device__ float  g_scale[HID];
__device__ float  g_shift[HID];

__device__ __forceinline__ float lrelu(float v) { return v > 0.f ? v : 0.2f * v; }

// ---------------- CSR build ----------------
__global__ void k_hist(const int* __restrict__ ei) {
    int e = blockIdx.x * blockDim.x + threadIdx.x;
    if (e >= ETOT) return;
    int d = (e < EE) ? ei[EE + e] : (e - EE);
    atomicAdd(&g_cnt[d], 1);
}
__global__ void k_scan_a() {   // 49 blocks x 1024
    __shared__ int sm[1024];
    int t = threadIdx.x;
    sm[t] = g_cnt[blockIdx.x * 1024 + t];
    __syncthreads();
    for (int o = 512; o; o >>= 1) {
        if (t < o) sm[t] += sm[t + o];
        __syncthreads();
    }
    if (t == 0) g_bsum[blockIdx.x] = sm[0];
}
__global__ void k_scan_b() {
    int acc = 0;
    for (int b = 0; b < 49; b++) { g_boff[b] = acc; acc += g_bsum[b]; }
}
__global__ void k_scan_c() {   // inclusive scan -> exclusive; self-zeroes g_cnt
    __shared__ int sm[1024];
    int t = threadIdx.x;
    int i = blockIdx.x * 1024 + t;
    int v = g_cnt[i];
    g_cnt[i] = 0;                      // restore precondition for next launch
    sm[t] = v;
    __syncthreads();
    for (int o = 1; o < 1024; o <<= 1) {
        int u = (t >= o) ? sm[t - o] : 0;
        __syncthreads();
        sm[t] += u;
        __syncthreads();
    }
    int ex = g_boff[blockIdx.x] + sm[t] - v;
    if (i <= NN) g_off[i] = ex;
    if (i < NN)  g_cur[i] = ex;
}
__global__ void k_fill(const int* __restrict__ ei) {
    int e = blockIdx.x * blockDim.x + threadIdx.x;
    if (e >= ETOT) return;
    int s, d;
    if (e < EE) { s = ei[e]; d = ei[EE + e]; } else { s = d = e - EE; }
    int pos = atomicAdd(&g_cur[d], 1);
    g_csr[pos] = s;
}

// ---------------- encoder ----------------
__global__ void k_encoder(const float* __restrict__ x, const float* __restrict__ w,
                          const float* __restrict__ b) {
    int i = blockIdx.x * blockDim.x + threadIdx.x;
    if (i >= NN * HID) return;
    int n = i / HID, c = i % HID;
    float acc = b[c];
#pragma unroll
    for (int k = 0; k < INC; k++) acc += x[n * INC + k] * w[k * HID + c];
    g_h[i] = acc;
}

// ---------------- transform: h@W (fp32 compute, fp16 store) + fused BN-in + es/ed ----------------
template <int DOUT, bool BNIN>
__global__ void __launch_bounds__(256)
k_transform2(const float* __restrict__ in, const float* __restrict__ W,
             const float* __restrict__ as_, const float* __restrict__ ad_) {
    constexpr int HD    = 4 * DOUT;
    constexpr int COLT  = HD / 4;
    constexpr int NGRP  = 256 / COLT;
    constexpr int NODES = NGRP * 8;
    constexpr int LPH   = DOUT / 4;
    __shared__ float sh[NODES * HID];

    int t = threadIdx.x;
    int nbase = blockIdx.x * NODES;

    for (int i = t; i < NODES * HID; i += 256) {
        int n = nbase + i / HID;
        int k = i % HID;
        float v = 0.f;
        if (n < NN) {
            v = in[n * HID + k];
            if (BNIN) v = fmaxf(fmaf(g_scale[k], v, g_shift[k]), 0.f);
        }
        sh[i] = v;
    }
    __syncthreads();

    int tx = t % COLT;
    int g  = t / COLT;
    int j0 = g * 8;

    float4 acc[8];
#pragma unroll
    for (int j = 0; j < 8; j++) acc[j] = make_float4(0.f, 0.f, 0.f, 0.f);

#pragma unroll 4
    for (int k = 0; k < HID; k++) {
        float4 wv = *(const float4*)&W[k * HD + 4 * tx];
#pragma unroll
        for (int j = 0; j < 8; j++) {
            float hv = sh[(j0 + j) * HID + k];
            acc[j].x = fmaf(hv, wv.x, acc[j].x);
            acc[j].y = fmaf(hv, wv.y, acc[j].y);
            acc[j].z = fmaf(hv, wv.z, acc[j].z);
            acc[j].w = fmaf(hv, wv.w, acc[j].w);
        }
    }

    float4 as4 = *(const float4*)&as_[4 * tx];
    float4 ad4 = *(const float4*)&ad_[4 * tx];
    int head = (4 * tx) / DOUT;

#pragma unroll
    for (int j = 0; j < 8; j++) {
        int n = nbase + j0 + j;
        if (n < NN) {
            __half2 p0 = __floats2half2_rn(acc[j].x, acc[j].y);
            __half2 p1 = __floats2half2_rn(acc[j].z, acc[j].w);
            uint2 u;
            u.x = *reinterpret_cast<unsigned*>(&p0);
            u.y = *reinterpret_cast<unsigned*>(&p1);
            *(uint2*)&g_hW[(size_t)n * (HD / 2) + 2 * tx] = u;
        }
        float pes = acc[j].x * as4.x + acc[j].y * as4.y + acc[j].z * as4.z + acc[j].w * as4.w;
        float ped = acc[j].x * ad4.x + acc[j].y * ad4.y + acc[j].z * ad4.z + acc[j].w * ad4.w;
#pragma unroll
        for (int o = LPH / 2; o; o >>= 1) {
            pes += __shfl_xor_sync(FULLM, pes, o);
            ped += __shfl_xor_sync(FULLM, ped, o);
        }
        if ((tx % LPH) == 0 && n < NN) {
            g_es[n * 4 + head] = pes;
            g_ed[n * 4 + head] = ped;
        }
    }
}

// ---------------- fused GAT aggregation: warp/dst, single pass, no max, fp16 values ----------------
__global__ void __launch_bounds__(256)
k_agg64() {
    int warp = threadIdx.x >> 5, lane = threadIdx.x & 31;
    int n = blockIdx.x * 8 + warp;
    if (n >= NN) return;
    int beg = g_off[n], end = g_off[n + 1];

    float edh = (lane < 4) ? g_ed[n * 4 + lane] : 0.f;
    const uint4* hw = (const uint4*)g_hW;  // 32 uint4 per row (256 halves)

    float sacc = 0.f;
    float a[8];
#pragma unroll
    for (int i = 0; i < 8; i++) a[i] = 0.f;

    for (int i = beg; i < end; i++) {
        int s = __ldg(&g_csr[i]);
        float ex = 0.f;
        if (lane < 4) {
            ex = expf(lrelu(g_es[s * 4 + lane] + edh));
            sacc += ex;
        }
        float exA = __shfl_sync(FULLM, ex, lane >> 3);
        uint4 v = hw[(size_t)s * 32 + lane];
        float2 f0 = __half22float2(*(__half2*)&v.x);
        float2 f1 = __half22float2(*(__half2*)&v.y);
        float2 f2 = __half22float2(*(__half2*)&v.z);
        float2 f3 = __half22float2(*(__half2*)&v.w);
        a[0] = fmaf(f0.x, exA, a[0]); a[1] = fmaf(f0.y, exA, a[1]);
        a[2] = fmaf(f1.x, exA, a[2]); a[3] = fmaf(f1.y, exA, a[3]);
        a[4] = fmaf(f2.x, exA, a[4]); a[5] = fmaf(f2.y, exA, a[5]);
        a[6] = fmaf(f3.x, exA, a[6]); a[7] = fmaf(f3.y, exA, a[7]);
    }

    float sA = __shfl_sync(FULLM, sacc, lane >> 3) + 1e-16f;
    float inv = 0.25f / sA;   // fold 1/HEADS mean
#pragma unroll
    for (int i = 0; i < 8; i++) a[i] *= inv;
#pragma unroll
    for (int i = 0; i < 8; i++) {
        a[i] += __shfl_xor_sync(FULLM, a[i], 8);
        a[i] += __shfl_xor_sync(FULLM, a[i], 16);
    }
    if (lane < 8) {
        *(float4*)&g_hn[n * 64 + 8 * lane]     = make_float4(a[0], a[1], a[2], a[3]);
        *(float4*)&g_hn[n * 64 + 8 * lane + 4] = make_float4(a[4], a[5], a[6], a[7]);
    }
}

__global__ void __launch_bounds__(256)
k_agg32() {
    int warp = threadIdx.x >> 5, lane = threadIdx.x & 31;
    int n = blockIdx.x * 8 + warp;
    if (n >= NN) return;
    int beg = g_off[n], end = g_off[n + 1];

    float edh = (lane < 4) ? g_ed[n * 4 + lane] : 0.f;
    const uint2* hw = (const uint2*)g_hW;  // 32 uint2 per row (128 halves)

    float sacc = 0.f;
    float a[4];
#pragma unroll
    for (int i = 0; i < 4; i++) a[i] = 0.f;

    for (int i = beg; i < end; i++) {
        int s = __ldg(&g_csr[i]);
        float ex = 0.f;
        if (lane < 4) {
            ex = expf(lrelu(g_es[s * 4 + lane] + edh));
            sacc += ex;
        }
        float exA = __shfl_sync(FULLM, ex, lane >> 3);
        uint2 v = hw[(size_t)s * 32 + lane];
        float2 f0 = __half22float2(*(__half2*)&v.x);
        float2 f1 = __half22float2(*(__half2*)&v.y);
        a[0] = fmaf(f0.x, exA, a[0]); a[1] = fmaf(f0.y, exA, a[1]);
        a[2] = fmaf(f1.x, exA, a[2]); a[3] = fmaf(f1.y, exA, a[3]);
    }

    float sA = __shfl_sync(FULLM, sacc, lane >> 3) + 1e-16f;
    float inv = 0.25f / sA;
#pragma unroll
    for (int i = 0; i < 4; i++) a[i] *= inv;
#pragma unroll
    for (int i = 0; i < 4; i++) {
        a[i] += __shfl_xor_sync(FULLM, a[i], 8);
        a[i] += __shfl_xor_sync(FULLM, a[i], 16);
    }
    if (lane < 8)
        *(float4*)&g_hn[n * 32 + 4 * lane] = make_float4(a[0], a[1], a[2], a[3]);
}

// ---------------- BatchNorm ----------------
template <int DOUT>
__global__ void __launch_bounds__(256)
k_bn_partial() {
    int tid = threadIdx.x;
    int c = tid % DOUT;
    float s = 0.f, q = 0.f;
    for (long i = (long)blockIdx.x * blockDim.x + tid; i < (long)NN * DOUT;
         i += (long)gridDim.x * blockDim.x) {
        float v = g_hn[i];
        s += v; q += v * v;
    }
    __shared__ float sm[256], qm[256];
    sm[tid] = s; qm[tid] = q;
    __syncthreads();
    for (int off = 128; off >= DOUT; off >>= 1) {
        if (tid < off) { sm[tid] += sm[tid + off]; qm[tid] += qm[tid + off]; }
        __syncthreads();
    }
    if (tid < DOUT) {
        atomicAdd(&g_bnsum[c], (double)sm[tid]);
        atomicAdd(&g_bnsq[c],  (double)qm[tid]);
    }
}
template <int DOUT>
__global__ void k_bn_finalize(const float* __restrict__ gamma, const float* __restrict__ beta) {
    int c = threadIdx.x;
    if (c >= DOUT) return;
    float mean = (float)(g_bnsum[c] / (double)NN);
    float var  = (float)(g_bnsq[c] / (double)NN) - mean * mean;
    var = fmaxf(var, 0.f);
    float sc = gamma[c] * rsqrtf(var + BN_EPS);
    g_scale[c] = sc;
    g_shift[c] = beta[c] - mean * sc;
    g_bnsum[c] = 0.0;   // restore precondition
    g_bnsq[c]  = 0.0;
}

// ---------------- fused: final BN apply + per-graph pooling + gemb + both heads ----------------
__global__ void __launch_bounds__(256)
k_pool_fused(const int* __restrict__ batch, float* __restrict__ out_h,
             float* __restrict__ out_gemb, float* __restrict__ out_eth,
             float* __restrict__ out_man,
             const float* __restrict__ ew1, const float* __restrict__ eb1,
             const float* __restrict__ ew2, const float* __restrict__ eb2,
             const float* __restrict__ mw1, const float* __restrict__ mb1,
             const float* __restrict__ mw2, const float* __restrict__ mb2) {
    int g = blockIdx.x;
    int t = threadIdx.x;
    // binary search group range [s0, s1)
    int l = 0, r = NN;
    while (l < r) { int m = (l + r) >> 1; if (batch[m] < g) l = m + 1; else r = m; }
    int s0 = l;
    l = s0; r = NN;
    while (l < r) { int m = (l + r) >> 1; if (batch[m] < g + 1) l = m + 1; else r = m; }
    int s1 = l;

    int c = t % 32, row = t / 32;
    float sc = g_scale[c], shf = g_shift[c];
    float sum = 0.f, mx = -FLT_MAX;
    for (int n = s0 + row; n < s1; n += 8) {
        float v = fmaf(sc, g_hn[n * 32 + c], shf);
        out_h[n * 32 + c] = v;
        sum += v;
        mx = fmaxf(mx, v);
    }
    __shared__ float ssum[256], smax[256];
    __shared__ float ge[32];
    ssum[t] = sum; smax[t] = mx;
    __syncthreads();
    for (int o = 128; o >= 32; o >>= 1) {
        if (t < o) { ssum[t] += ssum[t + o]; smax[t] = fmaxf(smax[t], smax[t + o]); }
        __syncthreads();
    }
    if (t < 32) {
        float cnt = (float)(s1 - s0);
        float sm = ssum[t];
        float mean = sm / fmaxf(cnt, 1.f);
        float mxv = (cnt > 0.f) ? smax[t] : 0.f;
        float v = (mean + mxv + sm) * (1.f / 3.f);
        out_gemb[g * 32 + t] = v;
        ge[t] = v;
    }
    __syncthreads();
    if (t < 32) {
        const float* w1 = (t < 16) ? ew1 : mw1;
        const float* b1 = (t < 16) ? eb1 : mb1;
        const float* w2 = (t < 16) ? ew2 : mw2;
        const float* b2 = (t < 16) ? eb2 : mb2;
        int j = t & 15;
        float a = b1[j];
#pragma unroll
        for (int k = 0; k < 32; k++) a = fmaf(ge[k], w1[k * 16 + j], a);
        float contrib = fmaxf(a, 0.f) * w2[j];
#pragma unroll
        for (int o = 8; o; o >>= 1) contrib += __shfl_xor_sync(FULLM, contrib, o);
        if (j == 0) {
            float oo = contrib + b2[0];
            float sig = 1.f / (1.f + expf(-oo));
            if (t < 16) out_eth[g] = sig; else out_man[g] = sig;
        }
    }
}

// ---------------- host ----------------
extern "C" void kernel_launch(void* const* d_in, const int* in_sizes, int n_in,
                              void* d_out, int out_size) {
    const float* x      = (const float*)d_in[0];
    const int*   ei     = (const int*)d_in[1];
    const int*   batch  = (const int*)d_in[2];
    const float* enc_w  = (const float*)d_in[3];
    const float* enc_b  = (const float*)d_in[4];
    const float* W0 = (const float*)d_in[5],  *A0s = (const float*)d_in[6],  *A0d = (const float*)d_in[7];
    const float* G0 = (const float*)d_in[9],  *B0  = (const float*)d_in[10];
    const float* W1 = (const float*)d_in[11], *A1s = (const float*)d_in[12], *A1d = (const float*)d_in[13];
    const float* G1 = (const float*)d_in[15], *B1  = (const float*)d_in[16];
    const float* W2 = (const float*)d_in[17], *A2s = (const float*)d_in[18], *A2d = (const float*)d_in[19];
    const float* G2 = (const float*)d_in[21], *B2  = (const float*)d_in[22];
    const float* ew1 = (const float*)d_in[23], *eb1 = (const float*)d_in[24];
    const float* ew2 = (const float*)d_in[25], *eb2 = (const float*)d_in[26];
    const float* mw1 = (const float*)d_in[27], *mb1 = (const float*)d_in[28];
    const float* mw2 = (const float*)d_in[29], *mb2 = (const float*)d_in[30];

    float* out      = (float*)d_out;
    float* out_h    = out;
    float* out_gemb = out + (size_t)NN * OUTC;
    float* out_eth  = out_gemb + GG * OUTC;
    float* out_man  = out_eth + GG;

    void *ph, *phn;
    cudaGetSymbolAddress(&ph,  g_h);
    cudaGetSymbolAddress(&phn, g_hn);

    // CSR build (g_cnt is self-zeroing via k_scan_c; zero-init at module load)
    k_hist<<<(ETOT + 255) / 256, 256>>>(ei);
    k_scan_a<<<49, 1024>>>();
    k_scan_b<<<1, 1>>>();
    k_scan_c<<<49, 1024>>>();
    k_fill<<<(ETOT + 255) / 256, 256>>>(ei);

    k_encoder<<<(NN * HID + 255) / 256, 256>>>(x, enc_w, enc_b);

    // Layer 0
    k_transform2<64, false><<<(NN + 31) / 32, 256>>>((const float*)ph, W0, A0s, A0d);
    k_agg64<<<(NN + 7) / 8, 256>>>();
    k_bn_partial<64><<<296, 256>>>();
    k_bn_finalize<64><<<1, 64>>>(G0, B0);

    // Layer 1
    k_transform2<64, true><<<(NN + 31) / 32, 256>>>((const float*)phn, W1, A1s, A1d);
    k_agg64<<<(NN + 7) / 8, 256>>>();
    k_bn_partial<64><<<296, 256>>>();
    k_bn_finalize<64><<<1, 64>>>(G1, B1);

    // Layer 2
    k_transform2<32, true><<<(NN + 63) / 64, 256>>>((const float*)phn, W2, A2s, A2d);
    k_agg32<<<(NN + 7) / 8, 256>>>();
    k_bn_partial<32><<<296, 256>>>();
    k_bn_finalize<32><<<1, 32>>>(G2, B2);

    // Fused BN apply + pooling + gemb + heads
    k_pool_fused<<<GG, 256>>>(batch, out_h, out_gemb, out_eth, out_man,
                              ew1, eb1, ew2, eb2, mw1, mb1, mw2, mb2);
}